// round 2
// baseline (speedup 1.0000x reference)
#include <cuda_runtime.h>

#define B_ 512
#define S_ 512
#define T_ 128
// START_ID = 0, END_ID = 1

__device__ float g_partial[B_];

__device__ __forceinline__ unsigned long long ffma2(unsigned long long a,
                                                    unsigned long long b,
                                                    unsigned long long c) {
    unsigned long long d;
    asm("fma.rn.f32x2 %0, %1, %2, %3;" : "=l"(d) : "l"(a), "l"(b), "l"(c));
    return d;
}

__global__ void __launch_bounds__(128, 2)
crf_block_kernel(const float* __restrict__ x, const int* __restrict__ tags,
                 const float* __restrict__ mask, const float* __restrict__ tr)
{
    const int b    = blockIdx.x;
    const int tid  = threadIdx.x;
    const int lane = tid & 31;
    const int wid  = tid >> 5;

    __shared__ __align__(16) float p_sh[T_];
    __shared__ float rb[4];
    __shared__ float d_sh;
    __shared__ int   tags_sh[S_];

    const float* xb   = x + (size_t)b * (S_ * T_);
    const float* mrow = mask + b * S_;
    const int*   tgb  = tags + b * S_;

    // ---- stage tags into smem (coalesced) ----
    #pragma unroll
    for (int k = 0; k < 4; k++) tags_sh[tid + k * 128] = tgb[tid + k * 128];

    // ---- length = sum(mask row) ----
    float ms = mrow[tid] + mrow[tid + 128] + mrow[tid + 256] + mrow[tid + 384];
    #pragma unroll
    for (int o = 16; o; o >>= 1) ms += __shfl_xor_sync(0xffffffffu, ms, o);
    if (lane == 0) rb[wid] = ms;
    __syncthreads();
    const int len = (int)(rb[0] + rb[1] + rb[2] + rb[3] + 0.5f);
    __syncthreads();

    // ---- gold score partial: sum_{t<len} x[b,t,tags[t+1]] + Tr[tags[t+1],tags[t]] ----
    float gold = 0.f;
    for (int t = tid; t < len; t += 128) {
        int t1 = tags_sh[t + 1];
        int t0 = tags_sh[t];
        gold += xb[t * T_ + t1] + tr[t1 * T_ + t0];
    }

    // ---- E = exp(Tr) : thread i holds row i, packed as f32x2 pairs in registers ----
    unsigned long long E2[64];
    const float* trowp = tr + tid * T_;
    #pragma unroll
    for (int k = 0; k < 64; k++) {
        float2 e;
        e.x = __expf(trowp[2 * k]);
        e.y = __expf(trowp[2 * k + 1]);
        E2[k] = *reinterpret_cast<unsigned long long*>(&e);
    }
    const float te = tr[1 * T_ + tid];  // Tr[END_ID=1, i]

    // alpha normalized: a[i] = alpha[i] - M, with a[0] == 0 maintained
    float a = (tid == 0) ? 0.f : -10000.f;  // START_ID = 0
    float M = 0.f;

    for (int t = 0; t < len; t++) {
        p_sh[tid] = __expf(a);
        float xv = xb[t * T_ + tid];      // prefetch, overlaps bar+matvec
        __syncthreads();                  // BAR1: p ready

        unsigned long long c0 = 0ull, c1 = 0ull, c2 = 0ull, c3 = 0ull;
        const longlong2* p4 = reinterpret_cast<const longlong2*>(p_sh);
        #pragma unroll
        for (int j = 0; j < 16; j++) {
            longlong2 pa = p4[2 * j];
            longlong2 pb = p4[2 * j + 1];
            c0 = ffma2(E2[4 * j + 0], (unsigned long long)pa.x, c0);
            c1 = ffma2(E2[4 * j + 1], (unsigned long long)pa.y, c1);
            c2 = ffma2(E2[4 * j + 2], (unsigned long long)pb.x, c2);
            c3 = ffma2(E2[4 * j + 3], (unsigned long long)pb.y, c3);
        }
        float2 f0 = *reinterpret_cast<float2*>(&c0);
        float2 f1 = *reinterpret_cast<float2*>(&c1);
        float2 f2 = *reinterpret_cast<float2*>(&c2);
        float2 f3 = *reinterpret_cast<float2*>(&c3);
        float s = ((f0.x + f0.y) + (f1.x + f1.y)) + ((f2.x + f2.y) + (f3.x + f3.y));

        float u = xv + __logf(s);         // alpha_new[i] - M_old
        if (tid == 0) d_sh = u;
        __syncthreads();                  // BAR2: matvec done (p reusable), d_sh ready
        float d = d_sh;
        a = u - d;                        // renormalize: a[0] -> 0
        M += d;
    }

    // ---- fwd = M + LSE_i(a[i] + Tr[END, i]) ----
    float v  = a + te;
    float mx = v;
    #pragma unroll
    for (int o = 16; o; o >>= 1) mx = fmaxf(mx, __shfl_xor_sync(0xffffffffu, mx, o));
    __syncthreads();
    if (lane == 0) rb[wid] = mx;
    __syncthreads();
    mx = fmaxf(fmaxf(rb[0], rb[1]), fmaxf(rb[2], rb[3]));
    float es = __expf(v - mx);
    #pragma unroll
    for (int o = 16; o; o >>= 1) es += __shfl_xor_sync(0xffffffffu, es, o);
    __syncthreads();
    if (lane == 0) rb[wid] = es;
    __syncthreads();
    float tot = rb[0] + rb[1] + rb[2] + rb[3];
    float fwd = M + mx + __logf(tot);

    // ---- gold reduce + final transition term ----
    #pragma unroll
    for (int o = 16; o; o >>= 1) gold += __shfl_xor_sync(0xffffffffu, gold, o);
    __syncthreads();
    if (lane == 0) rb[wid] = gold;
    __syncthreads();
    if (tid == 0) {
        float g = rb[0] + rb[1] + rb[2] + rb[3] + tr[1 * T_ + tags_sh[len]];
        g_partial[b] = fwd - g;
    }
}

__global__ void crf_finalize_kernel(float* __restrict__ out)
{
    int tid = threadIdx.x;  // 512 threads
    float v = g_partial[tid];
    #pragma unroll
    for (int o = 16; o; o >>= 1) v += __shfl_xor_sync(0xffffffffu, v, o);
    __shared__ float rb[16];
    if ((tid & 31) == 0) rb[tid >> 5] = v;
    __syncthreads();
    if (tid < 32) {
        float s = (tid < 16) ? rb[tid] : 0.f;
        #pragma unroll
        for (int o = 8; o; o >>= 1) s += __shfl_xor_sync(0xffffffffu, s, o);
        if (tid == 0) out[0] = s * (1.0f / 512.0f);
    }
}

extern "C" void kernel_launch(void* const* d_in, const int* in_sizes, int n_in,
                              void* d_out, int out_size)
{
    const float* x    = (const float*)d_in[0];
    const int*   tags = (const int*)d_in[1];
    const float* mask = (const float*)d_in[2];
    const float* tr   = (const float*)d_in[3];
    (void)in_sizes; (void)n_in; (void)out_size;

    crf_block_kernel<<<B_, 128>>>(x, tags, mask, tr);
    crf_finalize_kernel<<<1, 512>>>((float*)d_out);
}

// round 4
// speedup vs baseline: 1.1492x; 1.1492x over previous
#include <cuda_runtime.h>

#define B_ 512
#define S_ 512
#define T_ 128
// START_ID = 0, END_ID = 1

__device__ float g_partial[B_];

__device__ __forceinline__ unsigned long long ffma2(unsigned long long a,
                                                    unsigned long long b,
                                                    unsigned long long c) {
    unsigned long long d;
    asm("fma.rn.f32x2 %0, %1, %2, %3;" : "=l"(d) : "l"(a), "l"(b), "l"(c));
    return d;
}

__global__ void __launch_bounds__(128, 3)
crf_block_kernel(const float* __restrict__ x, const int* __restrict__ tags,
                 const float* __restrict__ mask, const float* __restrict__ tr)
{
    const int b    = blockIdx.x;
    const int tid  = threadIdx.x;
    const int lane = tid & 31;
    const int wid  = tid >> 5;

    __shared__ __align__(16) float p_sh[2][T_];
    __shared__ float d_sh[2];
    __shared__ float rb[4];
    __shared__ int   tags_sh[S_];

    const float* xb   = x + (size_t)b * (S_ * T_);
    const float* mrow = mask + b * S_;
    const int*   tgb  = tags + b * S_;

    // ---- stage tags into smem (coalesced) ----
    #pragma unroll
    for (int k = 0; k < 4; k++) tags_sh[tid + k * 128] = tgb[tid + k * 128];

    // ---- length = sum(mask row) ----
    float ms = mrow[tid] + mrow[tid + 128] + mrow[tid + 256] + mrow[tid + 384];
    #pragma unroll
    for (int o = 16; o; o >>= 1) ms += __shfl_xor_sync(0xffffffffu, ms, o);
    if (lane == 0) rb[wid] = ms;
    __syncthreads();
    const int len = (int)(rb[0] + rb[1] + rb[2] + rb[3] + 0.5f);
    __syncthreads();

    // ---- gold score partial: sum_{t<len} x[b,t,tags[t+1]] + Tr[tags[t+1],tags[t]] ----
    float gold = 0.f;
    for (int t = tid; t < len; t += 128) {
        int t1 = tags_sh[t + 1];
        int t0 = tags_sh[t];
        gold += xb[t * T_ + t1] + tr[t1 * T_ + t0];
    }

    // ---- E = exp(Tr) : thread i holds row i, packed as f32x2 pairs in registers ----
    unsigned long long E2[64];
    const float4* trow4 = reinterpret_cast<const float4*>(tr + tid * T_);
    #pragma unroll
    for (int k = 0; k < 32; k++) {
        float4 t4 = trow4[k];
        float2 ea, eb;
        ea.x = __expf(t4.x); ea.y = __expf(t4.y);
        eb.x = __expf(t4.z); eb.y = __expf(t4.w);
        E2[2 * k]     = *reinterpret_cast<unsigned long long*>(&ea);
        E2[2 * k + 1] = *reinterpret_cast<unsigned long long*>(&eb);
    }
    const float te = tr[1 * T_ + tid];  // Tr[END_ID=1, i]

    // State: a = alpha_i - M (kept small), c = lagged normalizer, M = frame offset.
    // p = exp(a - c) with exponent = alpha_i(t) - alpha_0(t-1), bounded ~|25|.
    float a = (tid == 0) ? 0.f : -10000.f;  // START_ID = 0
    float c = 0.f;
    float M = 0.f;
    float xv = xb[tid];                     // x[t=0]
    int buf = 0;

    for (int t = 0; t < len; t++) {
        float xn = xb[(t + 1) * T_ + tid];  // t+1 <= 510 < S_: always in-bounds; deep prefetch
        p_sh[buf][tid] = __expf(a - c);
        if (tid == 0) d_sh[buf] = a;
        __syncthreads();                    // single bar per step

        float a0 = d_sh[buf];
        unsigned long long c0 = 0ull, c1 = 0ull, c2 = 0ull, c3 = 0ull;
        const longlong2* p4 = reinterpret_cast<const longlong2*>(p_sh[buf]);
        #pragma unroll
        for (int j = 0; j < 16; j++) {
            longlong2 pa = p4[2 * j];
            longlong2 pb = p4[2 * j + 1];
            c0 = ffma2(E2[4 * j + 0], (unsigned long long)pa.x, c0);
            c1 = ffma2(E2[4 * j + 1], (unsigned long long)pa.y, c1);
            c2 = ffma2(E2[4 * j + 2], (unsigned long long)pb.x, c2);
            c3 = ffma2(E2[4 * j + 3], (unsigned long long)pb.y, c3);
        }
        float2 f0 = *reinterpret_cast<float2*>(&c0);
        float2 f1 = *reinterpret_cast<float2*>(&c1);
        float2 f2 = *reinterpret_cast<float2*>(&c2);
        float2 f3 = *reinterpret_cast<float2*>(&c3);
        float s = ((f0.x + f0.y) + (f1.x + f1.y)) + ((f2.x + f2.y) + (f3.x + f3.y));

        // s = sum_j E_ij exp(alpha_j - (M + c));  alpha_new = x + log(s) + M + c
        a = xv + __logf(s);   // new frame M' = M + c
        M += c;
        c = a0 - c;           // alpha_0(t) - M' : next step's lagged normalizer
        xv = xn;
        buf ^= 1;
    }

    // ---- fwd = M + LSE_i(a[i] + Tr[END, i]) ----
    float v  = a + te;
    float mx = v;
    #pragma unroll
    for (int o = 16; o; o >>= 1) mx = fmaxf(mx, __shfl_xor_sync(0xffffffffu, mx, o));
    __syncthreads();
    if (lane == 0) rb[wid] = mx;
    __syncthreads();
    mx = fmaxf(fmaxf(rb[0], rb[1]), fmaxf(rb[2], rb[3]));
    float es = __expf(v - mx);
    #pragma unroll
    for (int o = 16; o; o >>= 1) es += __shfl_xor_sync(0xffffffffu, es, o);
    __syncthreads();
    if (lane == 0) rb[wid] = es;
    __syncthreads();
    float tot = rb[0] + rb[1] + rb[2] + rb[3];
    float fwd = M + mx + __logf(tot);

    // ---- gold reduce + final transition term ----
    #pragma unroll
    for (int o = 16; o; o >>= 1) gold += __shfl_xor_sync(0xffffffffu, gold, o);
    __syncthreads();
    if (lane == 0) rb[wid] = gold;
    __syncthreads();
    if (tid == 0) {
        float g = rb[0] + rb[1] + rb[2] + rb[3] + tr[1 * T_ + tags_sh[len]];
        g_partial[b] = fwd - g;
    }
}

__global__ void crf_finalize_kernel(float* __restrict__ out)
{
    int tid = threadIdx.x;  // 512 threads
    float v = g_partial[tid];
    #pragma unroll
    for (int o = 16; o; o >>= 1) v += __shfl_xor_sync(0xffffffffu, v, o);
    __shared__ float rb[16];
    if ((tid & 31) == 0) rb[tid >> 5] = v;
    __syncthreads();
    if (tid < 32) {
        float s = (tid < 16) ? rb[tid] : 0.f;
        #pragma unroll
        for (int o = 8; o; o >>= 1) s += __shfl_xor_sync(0xffffffffu, s, o);
        if (tid == 0) out[0] = s * (1.0f / 512.0f);
    }
}

extern "C" void kernel_launch(void* const* d_in, const int* in_sizes, int n_in,
                              void* d_out, int out_size)
{
    const float* x    = (const float*)d_in[0];
    const int*   tags = (const int*)d_in[1];
    const float* mask = (const float*)d_in[2];
    const float* tr   = (const float*)d_in[3];
    (void)in_sizes; (void)n_in; (void)out_size;

    crf_block_kernel<<<B_, 128>>>(x, tags, mask, tr);
    crf_finalize_kernel<<<1, 512>>>((float*)d_out);
}